// round 10
// baseline (speedup 1.0000x reference)
#include <cuda_runtime.h>
#include <cuda_bf16.h>
#include <cstdint>

// ---------------- problem constants ----------------
#define S_ROWS 16384
#define K_DIM  1024
#define D_TOT  6400
#define BINS   20

// ---------------- tiling ----------------
#define BM 128
#define BN 128
#define BK 32
#define STAGES 3
#define KT (K_DIM / BK)          // 32
#define NTHREADS 256             // 8 warps: 2 (M) x 4 (N), warp tile 64x32

#define PLANE 8192               // 128 rows x 32 bf16 (64B) = 8KB
#define STAGE_B (4 * PLANE)      // Ahi, Alo, Bhi, Blo = 32KB
#define OFF_META (STAGES * STAGE_B)          // 98304
#define SMEM_TOTAL (OFF_META + 3 * BN * 4)   // 99840 -> 2 CTAs/SM

// ---------------- global scratch ----------------
__device__ __nv_bfloat16 g_xhi[S_ROWS * K_DIM];
__device__ __nv_bfloat16 g_xlo[S_ROWS * K_DIM];
__device__ __nv_bfloat16 g_whi[D_TOT * K_DIM];
__device__ __nv_bfloat16 g_wlo[D_TOT * K_DIM];
__device__ float g_hist[D_TOT * BINS];

// ---------------- helpers ----------------
__device__ __forceinline__ uint32_t smem_u32(const void* p) {
    uint32_t a;
    asm("{ .reg .u64 t; cvta.to.shared.u64 t, %1; cvt.u32.u64 %0, t; }"
        : "=r"(a) : "l"(p));
    return a;
}
// swizzle for 64B rows: XOR 16B-chunk bits [5:4] with row bits [8:7]
__device__ __forceinline__ uint32_t sw64(uint32_t off) {
    return off ^ ((off >> 3) & 0x30);
}
__device__ __forceinline__ void cp16(uint32_t s, const void* g) {
    asm volatile("cp.async.cg.shared.global [%0], [%1], 16;" :: "r"(s), "l"(g));
}
#define CP_COMMIT() asm volatile("cp.async.commit_group;" ::: "memory")
#define CP_WAIT(n)  asm volatile("cp.async.wait_group %0;" :: "n"(n) : "memory")

__device__ __forceinline__ void ldsm4(uint32_t* r, uint32_t addr) {
    asm volatile("ldmatrix.sync.aligned.m8n8.x4.shared.b16 {%0,%1,%2,%3}, [%4];"
        : "=r"(r[0]), "=r"(r[1]), "=r"(r[2]), "=r"(r[3]) : "r"(addr));
}
__device__ __forceinline__ void mma_bf16(float* d, const uint32_t* a,
                                         uint32_t b0, uint32_t b1) {
    asm volatile(
        "mma.sync.aligned.m16n8k16.row.col.f32.bf16.bf16.f32 "
        "{%0,%1,%2,%3}, {%4,%5,%6,%7}, {%8,%9}, {%0,%1,%2,%3};"
        : "+f"(d[0]), "+f"(d[1]), "+f"(d[2]), "+f"(d[3])
        : "r"(a[0]), "r"(a[1]), "r"(a[2]), "r"(a[3]), "r"(b0), "r"(b1));
}

// ---------------- pre-split: fp32 -> bf16 hi/lo planes ----------------
__global__ void split_kernel(const float4* __restrict__ src,
                             uint2* __restrict__ hi, uint2* __restrict__ lo, int n4)
{
    int i = blockIdx.x * blockDim.x + threadIdx.x;
    if (i >= n4) return;
    float4 v = src[i];
    uint32_t h0, h1, g0, g1;
    asm("cvt.rn.bf16x2.f32 %0, %1, %2;" : "=r"(h0) : "f"(v.y), "f"(v.x));
    asm("cvt.rn.bf16x2.f32 %0, %1, %2;" : "=r"(h1) : "f"(v.w), "f"(v.z));
    float l0 = v.x - __uint_as_float(h0 << 16);
    float l1 = v.y - __uint_as_float(h0 & 0xFFFF0000u);
    float l2 = v.z - __uint_as_float(h1 << 16);
    float l3 = v.w - __uint_as_float(h1 & 0xFFFF0000u);
    asm("cvt.rn.bf16x2.f32 %0, %1, %2;" : "=r"(g0) : "f"(l1), "f"(l0));
    asm("cvt.rn.bf16x2.f32 %0, %1, %2;" : "=r"(g1) : "f"(l3), "f"(l2));
    hi[i] = make_uint2(h0, h1);
    lo[i] = make_uint2(g0, g1);
}

__global__ void zero_hist_kernel() {
    int i = blockIdx.x * blockDim.x + threadIdx.x;
    if (i < D_TOT * BINS) g_hist[i] = 0.0f;
}

// ---------------- fused GEMM + histogram ----------------
__global__ __launch_bounds__(NTHREADS, 2)
void gemm_hist_kernel(const float* __restrict__ mins, const float* __restrict__ maxs)
{
    extern __shared__ char smem[];
    const uint32_t sb = smem_u32(smem);
    const int tid  = threadIdx.x;
    const int wid  = tid >> 5;
    const int lane = tid & 31;
    const int wm = wid & 1;          // warp M index (0..1) -> rows wm*64
    const int wn = wid >> 1;         // warp N index (0..3) -> cols wn*32

    const int m0  = blockIdx.y * BM;
    const int n0t = blockIdx.x * BN;

    const __nv_bfloat16* Ah = g_xhi + (size_t)m0 * K_DIM;
    const __nv_bfloat16* Al = g_xlo + (size_t)m0 * K_DIM;
    const __nv_bfloat16* Bh = g_whi + (size_t)n0t * K_DIM;
    const __nv_bfloat16* Bl = g_wlo + (size_t)n0t * K_DIM;

    float* mnS = (float*)(smem + OFF_META);
    float* mxS = mnS + BN;
    float* scS = mxS + BN;
    if (tid < BN) {
        float mn = mins[n0t + tid], mx = maxs[n0t + tid];
        mnS[tid] = mn; mxS[tid] = mx;
        scS[tid] = (float)BINS / (mx - mn);
    }

    // loader geometry: thread t covers row t>>1, 32B half (t&1), 2 chunks of 16B
    const int lrow  = tid >> 1;            // 0..127
    const int lhalf = tid & 1;             // 0..1

    auto load_stage = [&](int kt) {
        const uint32_t st = sb + (uint32_t)((kt % STAGES) * STAGE_B);
        const size_t kb = (size_t)kt * BK + lhalf * 16;
        const size_t goA = (size_t)lrow * K_DIM + kb;
        #pragma unroll
        for (int i = 0; i < 2; ++i) {
            uint32_t soff = sw64((uint32_t)(lrow * 64 + lhalf * 32 + i * 16));
            cp16(st + 0 * PLANE + soff, Ah + goA + i * 8);
            cp16(st + 1 * PLANE + soff, Al + goA + i * 8);
            cp16(st + 2 * PLANE + soff, Bh + goA + i * 8);
            cp16(st + 3 * PLANE + soff, Bl + goA + i * 8);
        }
    };

    float acc[4][4][4];
    #pragma unroll
    for (int i = 0; i < 4; ++i)
        #pragma unroll
        for (int j = 0; j < 4; ++j)
            #pragma unroll
            for (int r = 0; r < 4; ++r) acc[i][j][r] = 0.0f;

    load_stage(0); CP_COMMIT();
    load_stage(1); CP_COMMIT();

    const int l15   = lane & 15;
    const int khalf = (lane >> 4) << 4;   // k-half byte offset (0 or 16)

    for (int kt = 0; kt < KT; ++kt) {
        if (kt < KT - 1) { CP_WAIT(1); } else { CP_WAIT(0); }
        __syncthreads();                  // stage kt resident; stage kt-1 consumed
        if (kt + 2 < KT) { load_stage(kt + 2); CP_COMMIT(); }

        const uint32_t st = sb + (uint32_t)((kt % STAGES) * STAGE_B);
        #pragma unroll
        for (int ks = 0; ks < BK / 16; ++ks) {
            uint32_t bfr[2][2][4];
            #pragma unroll
            for (int p = 0; p < 2; ++p)
                #pragma unroll
                for (int ng = 0; ng < 2; ++ng) {
                    int nrow = wn * 32 + ng * 16 + l15;
                    uint32_t off = (uint32_t)(nrow * 64 + ks * 32) + khalf;
                    ldsm4(bfr[p][ng], st + (2 + p) * PLANE + sw64(off));
                }
            #pragma unroll
            for (int mf = 0; mf < 4; ++mf) {
                uint32_t af[2][4];
                int arow = wm * 64 + mf * 16 + l15;
                uint32_t off = (uint32_t)(arow * 64 + ks * 32) + khalf;
                ldsm4(af[0], st + 0 * PLANE + sw64(off));
                ldsm4(af[1], st + 1 * PLANE + sw64(off));
                #pragma unroll
                for (int nf = 0; nf < 4; ++nf) {
                    int ng = nf >> 1, h = nf & 1;
                    mma_bf16(acc[mf][nf], af[0], bfr[0][ng][h], bfr[0][ng][2 + h]);
                    mma_bf16(acc[mf][nf], af[0], bfr[1][ng][h], bfr[1][ng][2 + h]);
                    mma_bf16(acc[mf][nf], af[1], bfr[0][ng][h], bfr[0][ng][2 + h]);
                }
            }
        }
    }
    __syncthreads();

    // ---------------- histogram epilogue ----------------
    // 8 warp-private hists of 32 cols x 20 bins (warp covers cols wn*32..+31)
    float* hall = (float*)smem;                 // 8 x 32 x 20 floats = 20KB
    for (int i = tid; i < 8 * 32 * BINS; i += NTHREADS) hall[i] = 0.0f;
    __syncthreads();

    float* hw = hall + wid * (32 * BINS);
    const int q = lane & 3;
    #pragma unroll
    for (int nf = 0; nf < 4; ++nf) {
        #pragma unroll
        for (int half = 0; half < 2; ++half) {
            int lc = nf * 8 + 2 * q + half;      // col within warp's 32
            int c  = wn * 32 + lc;
            float mn = mnS[c], mx = mxS[c], sc = scS[c];
            #pragma unroll
            for (int mf = 0; mf < 4; ++mf)
                #pragma unroll
                for (int rp = 0; rp < 2; ++rp) {
                    float p = acc[mf][nf][2 * rp + half];
                    if (p >= mn && p <= mx) {
                        int b = min((int)((p - mn) * sc), BINS - 1);
                        atomicAdd(&hw[lc * BINS + b], 1.0f);
                    }
                }
        }
    }
    __syncthreads();

    // merge the 2 warp copies per column group -> global atomics
    for (int i = tid; i < BN * BINS; i += NTHREADS) {
        int c = i / BINS, b = i - c * BINS;
        int cwn = c >> 5, lc = c & 31;
        float s = hall[(cwn * 2 + 0) * (32 * BINS) + lc * BINS + b]
                + hall[(cwn * 2 + 1) * (32 * BINS) + lc * BINS + b];
        if (s != 0.0f)
            atomicAdd(&g_hist[(size_t)n0t * BINS + i], s);
    }
}

// ---------------- normalize ----------------
__global__ void normalize_kernel(float* __restrict__ out)
{
    int row  = blockIdx.x * 4 + (threadIdx.x >> 5);
    int lane = threadIdx.x & 31;
    if (row >= D_TOT) return;
    float v = (lane < BINS) ? g_hist[row * BINS + lane] : 0.0f;
    float s = v * v;
    #pragma unroll
    for (int o = 16; o; o >>= 1) s += __shfl_xor_sync(0xFFFFFFFFu, s, o);
    float denom = fmaxf(sqrtf(s), 1e-12f);
    if (lane < BINS) out[row * BINS + lane] = v / denom;
}

extern "C" void kernel_launch(void* const* d_in, const int* in_sizes, int n_in,
                              void* d_out, int out_size)
{
    const float* x    = (const float*)d_in[0];
    const float* W    = (const float*)d_in[1];
    const float* mins = (const float*)d_in[2];
    const float* maxs = (const float*)d_in[3];
    float* out = (float*)d_out;

    static int attr_set = 0;
    if (!attr_set) {
        cudaFuncSetAttribute(gemm_hist_kernel,
                             cudaFuncAttributeMaxDynamicSharedMemorySize, SMEM_TOTAL);
        attr_set = 1;
    }

    __nv_bfloat16 *xhi, *xlo, *whi, *wlo;
    cudaGetSymbolAddress((void**)&xhi, g_xhi);
    cudaGetSymbolAddress((void**)&xlo, g_xlo);
    cudaGetSymbolAddress((void**)&whi, g_whi);
    cudaGetSymbolAddress((void**)&wlo, g_wlo);

    int nx4 = S_ROWS * K_DIM / 4;
    int nw4 = D_TOT * K_DIM / 4;
    split_kernel<<<(nx4 + 255) / 256, 256>>>((const float4*)x, (uint2*)xhi, (uint2*)xlo, nx4);
    split_kernel<<<(nw4 + 255) / 256, 256>>>((const float4*)W, (uint2*)whi, (uint2*)wlo, nw4);
    zero_hist_kernel<<<(D_TOT * BINS + 255) / 256, 256>>>();

    dim3 grid(D_TOT / BN, S_ROWS / BM);   // (50, 128)
    gemm_hist_kernel<<<grid, NTHREADS, SMEM_TOTAL>>>(mins, maxs);

    normalize_kernel<<<(D_TOT + 3) / 4, 128>>>(out);
}